// round 9
// baseline (speedup 1.0000x reference)
#include <cuda_runtime.h>
#include <math.h>
#include <stdint.h>
#include <stddef.h>

// ---------------- problem constants ----------------
#define BSZ 2
#define HH 96
#define WW 96
#define LS 9216          // H*W
#define CC 96            // d_model
#define DD 192           // d_inner
#define NS 16            // d_state
#define KD 4             // K directions
#define RR 6             // dt_rank
#define XD 152           // stacked x_proj output dim
#define NCH 96           // number of chunks
#define CHL 96           // chunk length
#define MPIX (BSZ*LS)    // 18432

typedef unsigned long long u64;

// ---------------- scratch ----------------
__device__ float g_xz   [BSZ*LS*2*DD];
__device__ float g_u    [BSZ*LS*DD];
__device__ float g_xdbl [BSZ*LS*XD];
__device__ float g_P    [BSZ*KD*NCH*DD*NS];
__device__ float g_hend [BSZ*KD*NCH*DD*NS];
__device__ float g_oy   [BSZ*KD*LS*DD];
__device__ float g_ypost[BSZ*LS*DD];
__device__ float g_t96  [BSZ*LS*CC];
__device__ float g_x2   [BSZ*LS*CC];
__device__ float g_h1n  [BSZ*LS*CC];
__device__ float g_t192 [BSZ*LS*DD];

// ---------------- f32x2 packed helpers ----------------
__device__ __forceinline__ u64 pk2(float lo, float hi) {
    u64 r;
    asm("mov.b64 %0, {%1, %2};" : "=l"(r) : "r"(__float_as_uint(lo)), "r"(__float_as_uint(hi)));
    return r;
}
__device__ __forceinline__ u64 dup2(float v) {
    u64 r;
    asm("mov.b64 %0, {%1, %1};" : "=l"(r) : "r"(__float_as_uint(v)));
    return r;
}
__device__ __forceinline__ u64 fma2(u64 a, u64 b, u64 c) {
    u64 d;
    asm("fma.rn.f32x2 %0, %1, %2, %3;" : "=l"(d) : "l"(a), "l"(b), "l"(c));
    return d;
}
__device__ __forceinline__ u64 mul2(u64 a, u64 b) {
    u64 d;
    asm("mul.rn.f32x2 %0, %1, %2;" : "=l"(d) : "l"(a), "l"(b));
    return d;
}
__device__ __forceinline__ void unpk2(u64 v, float& lo, float& hi) {
    unsigned int a, b;
    asm("mov.b64 {%0, %1}, %2;" : "=r"(a), "=r"(b) : "l"(v));
    lo = __uint_as_float(a); hi = __uint_as_float(b);
}

// ---------------- math helpers ----------------
__device__ __forceinline__ float siluf(float x) {
    return x / (1.f + __expf(-x));
}
// affine scan-position parameters: position p(s) = p0 + s*pstep (valid since CHL==HH==WW==96)
__device__ __forceinline__ void scan_affine(int k, int c, int& p0, int& pstep) {
    if (k == 0)      { p0 = c * 96;                pstep = 1;   }
    else if (k == 1) { p0 = c;                     pstep = 96;  }
    else if (k == 2) { p0 = (95 - c) * 96 + 95;    pstep = -1;  }
    else             { p0 = 95 * 96 + (95 - c);    pstep = -96; }
}

// ================= fused LN + in_proj GEMM =================
// out[p, n] = sum_c LN(x)[p,c] * W[n,c] + bias[n]
// computed as: inv_p * (sum_c v*(W*g) - m_p * sum_c (W*g)) + sum_c W*b + bias
__global__ void __launch_bounds__(256) gemm_ln_in(const float* __restrict__ x,
                                                  const float* __restrict__ lng,
                                                  const float* __restrict__ lnb,
                                                  const float* __restrict__ W,
                                                  const float* __restrict__ bias,
                                                  float* __restrict__ C) {
    __shared__ __align__(16) float As[96][130];    // raw x tile, channel-major
    __shared__ __align__(16) u64   Ws2[16][66];    // dup'd, g-scaled W slab
    __shared__ float pm[128], pinv[128];
    __shared__ float wgs[64], wbs[64];
    __shared__ float rb1[256], rb2[256];

    const int N = 2 * DD;   // 384
    int t = threadIdx.x;
    int bn = blockIdx.x * 64, bm = blockIdx.y * 128;
    int b = bm / LS, p0 = bm - b * LS;

    // --- load raw A tile (128 pixels x 96 channels) + per-pixel partial stats ---
    int i = t & 127;
    float s = 0.f, ss = 0.f;
#pragma unroll
    for (int rep = 0; rep < 48; rep++) {
        int c = rep * 2 + (t >> 7);
        float v = x[((size_t)(b * CC + c)) * LS + p0 + i];
        As[c][i] = v;
        s += v; ss += v * v;
    }
    rb1[t] = s; rb2[t] = ss;
    __syncthreads();
    if (t < 128) {
        float su = rb1[t] + rb1[t + 128];
        float sq = rb2[t] + rb2[t + 128];
        float m = su * (1.f / CC);
        float var = sq * (1.f / CC) - m * m;
        pm[t] = m;
        pinv[t] = rsqrtf(var + 1e-6f);
    }

    int tx = t & 15, ty = t >> 4;
    int m0 = ty * 8;
    int lrow = t >> 2, lc4 = t & 3;

    u64 acc[4][4];
#pragma unroll
    for (int ii = 0; ii < 4; ii++)
#pragma unroll
        for (int j = 0; j < 4; j++) acc[ii][j] = 0ull;

    float wg_part = 0.f, wb_part = 0.f;

    for (int k0 = 0; k0 < CC; k0 += 16) {
        // stage g-scaled, duplicated W: n=lrow (0..63), kk=lc4*4..+3
        float4 wv = *(const float4*)&W[(size_t)(bn + lrow) * CC + k0 + lc4 * 4];
        float g0 = lng[k0 + lc4 * 4 + 0], g1 = lng[k0 + lc4 * 4 + 1];
        float g2 = lng[k0 + lc4 * 4 + 2], g3 = lng[k0 + lc4 * 4 + 3];
        float b0 = lnb[k0 + lc4 * 4 + 0], b1 = lnb[k0 + lc4 * 4 + 1];
        float b2 = lnb[k0 + lc4 * 4 + 2], b3 = lnb[k0 + lc4 * 4 + 3];
        float w0 = wv.x * g0, w1 = wv.y * g1, w2 = wv.z * g2, w3 = wv.w * g3;
        Ws2[lc4 * 4 + 0][lrow] = dup2(w0);
        Ws2[lc4 * 4 + 1][lrow] = dup2(w1);
        Ws2[lc4 * 4 + 2][lrow] = dup2(w2);
        Ws2[lc4 * 4 + 3][lrow] = dup2(w3);
        wg_part += w0 + w1 + w2 + w3;
        wb_part += wv.x * b0 + wv.y * b1 + wv.z * b2 + wv.w * b3;
        __syncthreads();
#pragma unroll
        for (int kk = 0; kk < 16; kk++) {
            u64 a[4], wp[4];
#pragma unroll
            for (int ii = 0; ii < 4; ii++) a[ii] = *(const u64*)&As[k0 + kk][m0 + 2 * ii];
#pragma unroll
            for (int j = 0; j < 4; j++) wp[j] = Ws2[kk][tx + 16 * j];
#pragma unroll
            for (int ii = 0; ii < 4; ii++)
#pragma unroll
                for (int j = 0; j < 4; j++) acc[ii][j] = fma2(a[ii], wp[j], acc[ii][j]);
        }
        __syncthreads();
    }
    // combine per-column sums over lc4 (lanes t^1, t^2 share lrow)
    wg_part += __shfl_xor_sync(~0u, wg_part, 1);
    wg_part += __shfl_xor_sync(~0u, wg_part, 2);
    wb_part += __shfl_xor_sync(~0u, wb_part, 1);
    wb_part += __shfl_xor_sync(~0u, wb_part, 2);
    if (lc4 == 0) { wgs[lrow] = wg_part; wbs[lrow] = wb_part; }
    __syncthreads();

    // epilogue
#pragma unroll
    for (int j = 0; j < 4; j++) {
        int n = bn + tx + 16 * j;
        float WG = wgs[tx + 16 * j];
        float WB = wbs[tx + 16 * j] + bias[n];
        u64 nWG = dup2(-WG), WBd = dup2(WB);
#pragma unroll
        for (int ii = 0; ii < 4; ii++) {
            int m = m0 + 2 * ii;
            u64 pm2 = *(const u64*)&pm[0] ; // placeholder avoided; explicit pack below
            pm2 = pk2(pm[m], pm[m + 1]);
            u64 pi2 = pk2(pinv[m], pinv[m + 1]);
            u64 t1 = fma2(nWG, pm2, acc[ii][j]);
            u64 val = fma2(t1, pi2, WBd);
            float lo, hi;
            unpk2(val, lo, hi);
            C[(size_t)(bm + m) * N + n] = lo;
            C[(size_t)(bm + m + 1) * N + n] = hi;
        }
    }
}

// ================= generic f32x2 GEMM (dup'd W, conflict-free wp) =================
// C[m,n] = act(sum_k A[m,k]*W[n,k] + bias[n]); M%128==0, K%16==0
template <int ACT>
__global__ void __launch_bounds__(256) gemm2(const float* __restrict__ A, const float* __restrict__ W,
                                             const float* __restrict__ bias, float* __restrict__ C,
                                             int M, int N, int K) {
    __shared__ __align__(16) float As[16][130];
    __shared__ __align__(16) u64   Ws2[16][66];
    int t = threadIdx.x;
    int bn = blockIdx.x * 64, bm = blockIdx.y * 128;
    int tx = t & 15, ty = t >> 4;
    int m0 = ty * 8;

    u64 acc[4][4];
#pragma unroll
    for (int i = 0; i < 4; i++)
#pragma unroll
        for (int j = 0; j < 4; j++) acc[i][j] = 0ull;

    int lrow = t >> 2, lc4 = t & 3;

    for (int k0 = 0; k0 < K; k0 += 16) {
#pragma unroll
        for (int r = 0; r < 2; r++) {
            int row = lrow + r * 64;
            float4 v = *(const float4*)&A[(size_t)(bm + row) * K + k0 + lc4 * 4];
            As[lc4 * 4 + 0][row] = v.x; As[lc4 * 4 + 1][row] = v.y;
            As[lc4 * 4 + 2][row] = v.z; As[lc4 * 4 + 3][row] = v.w;
        }
        {
            float4 v = make_float4(0.f, 0.f, 0.f, 0.f);
            if (bn + lrow < N) v = *(const float4*)&W[(size_t)(bn + lrow) * K + k0 + lc4 * 4];
            Ws2[lc4 * 4 + 0][lrow] = dup2(v.x);
            Ws2[lc4 * 4 + 1][lrow] = dup2(v.y);
            Ws2[lc4 * 4 + 2][lrow] = dup2(v.z);
            Ws2[lc4 * 4 + 3][lrow] = dup2(v.w);
        }
        __syncthreads();
#pragma unroll
        for (int kk = 0; kk < 16; kk++) {
            u64 a[4], wp[4];
#pragma unroll
            for (int i = 0; i < 4; i++) a[i] = *(const u64*)&As[kk][m0 + 2 * i];
#pragma unroll
            for (int j = 0; j < 4; j++) wp[j] = Ws2[kk][tx + 16 * j];
#pragma unroll
            for (int i = 0; i < 4; i++)
#pragma unroll
                for (int j = 0; j < 4; j++) acc[i][j] = fma2(a[i], wp[j], acc[i][j]);
        }
        __syncthreads();
    }
#pragma unroll
    for (int j = 0; j < 4; j++) {
        int n = bn + tx + 16 * j;
        if (n >= N) continue;
        float bv = bias ? bias[n] : 0.f;
#pragma unroll
        for (int i = 0; i < 4; i++) {
            float lo, hi;
            unpk2(acc[i][j], lo, hi);
            lo += bv; hi += bv;
            if (ACT == 1) {
                lo = lo >= 0.f ? lo : 0.01f * lo;
                hi = hi >= 0.f ? hi : 0.01f * hi;
            }
            int m = bm + m0 + 2 * i;
            C[(size_t)m * N + n] = lo;
            C[(size_t)(m + 1) * N + n] = hi;
        }
    }
}

// ---------------- depthwise 3x3 conv + bias + SiLU ----------------
__global__ void __launch_bounds__(DD) conv_silu_kernel(const float* __restrict__ cw,
                                                       const float* __restrict__ cb) {
    int blk = blockIdx.x;
    int b = blk / LS, p = blk - b * LS;
    int d = threadIdx.x;
    int h = p / WW, w = p - h * WW;
    float acc = cb[d];
#pragma unroll
    for (int ky = 0; ky < 3; ky++) {
        int hh = h + ky - 1;
        if (hh < 0 || hh >= HH) continue;
#pragma unroll
        for (int kx = 0; kx < 3; kx++) {
            int ww2 = w + kx - 1;
            if (ww2 < 0 || ww2 >= WW) continue;
            acc += g_xz[((size_t)(b * LS + hh * WW + ww2)) * (2 * DD) + d] * cw[d * 9 + ky * 3 + kx];
        }
    }
    g_u[((size_t)(b * LS + p)) * DD + d] = siluf(acc);
}

// ---------------- per-step scan core helpers ----------------
// sv -> (delta, f=exp(-delta)) with one exp: f = sigmoid(-sv)
__device__ __forceinline__ void delta_f(float sv, float& delta, float& f) {
    float e = __expf(-fabsf(sv));
    delta = fmaxf(sv, 0.f) + log1pf(e);
    float num = (sv >= 0.f) ? e : 1.f;
    f = __fdividef(num, 1.f + e);
}
// powers (f^1..f^16) packed as 8 f32x2 via log-depth tree
__device__ __forceinline__ void pow_tree(float f, u64 q[8]) {
    float f2 = f * f, f4 = f2 * f2, f8 = f4 * f4;
    u64 d2 = dup2(f2), d4 = dup2(f4), d8 = dup2(f8);
    q[0] = pk2(f, f2);
    q[1] = mul2(q[0], d2);
    q[2] = mul2(q[0], d4);
    q[3] = mul2(q[1], d4);
    q[4] = mul2(q[0], d8);
    q[5] = mul2(q[1], d8);
    q[6] = mul2(q[2], d8);
    q[7] = mul2(q[3], d8);
}

// ---------------- scan phase 1: chunk decay + local end state ----------------
__global__ void __launch_bounds__(DD) scan_p1(const float* __restrict__ dtw,
                                              const float* __restrict__ dtb,
                                              const float* __restrict__ Alogs) {
    int blk = blockIdx.x;
    int c = blk % NCH;
    int k = (blk / NCH) % KD;
    int b = blk / (NCH * KD);
    int d = threadIdx.x;

    u64 wd2[3];
#pragma unroll
    for (int r = 0; r < 3; r++)
        wd2[r] = pk2(dtw[(k * DD + d) * RR + 2 * r], dtw[(k * DD + d) * RR + 2 * r + 1]);
    float bdt = dtb[k * DD + d];
    float A[NS];
    bool powok = true;
#pragma unroll
    for (int n = 0; n < NS; n++) {
        float an = __expf(Alogs[(k * DD + d) * NS + n]);
        A[n] = -an;
        powok = powok && (fabsf(an - (float)(n + 1)) < 1e-3f * (float)(n + 1));
    }

    int p0, pstep;
    scan_affine(k, c, p0, pstep);

    __shared__ __align__(16) float sx[CHL][40];
    for (int i = d; i < CHL * 38; i += DD) {
        int s = i / 38, cc = i - s * 38;
        sx[s][cc] = g_xdbl[((size_t)(b * LS + p0 + s * pstep)) * XD + k * 38 + cc];
    }
    __syncthreads();

    const float* up = g_u + ((size_t)(b * LS + p0)) * DD + d;
    int ustep = pstep * DD;
    float S = 0.f;
    u64 h2[8];
#pragma unroll
    for (int j = 0; j < 8; j++) h2[j] = 0ull;

    if (powok) {
        for (int s = 0; s < CHL; s++) {
            float uu = *up; up += ustep;
            u64 sv2 = fma2(*(const u64*)&sx[s][0], wd2[0],
                      fma2(*(const u64*)&sx[s][2], wd2[1],
                      mul2(*(const u64*)&sx[s][4], wd2[2])));
            float svlo, svhi; unpk2(sv2, svlo, svhi);
            float sv = svlo + svhi + bdt;
            float delta, f;
            delta_f(sv, delta, f);
            S += delta;
            u64 q[8];
            pow_tree(f, q);
            u64 dud = dup2(delta * uu);
#pragma unroll
            for (int j = 0; j < 8; j++) {
                u64 Bp = *(const u64*)&sx[s][6 + 2 * j];
                h2[j] = fma2(h2[j], q[j], mul2(dud, Bp));
            }
        }
    } else {
        float h[NS];
#pragma unroll
        for (int n = 0; n < NS; n++) h[n] = 0.f;
        for (int s = 0; s < CHL; s++) {
            float uu = *up; up += ustep;
            u64 sv2 = fma2(*(const u64*)&sx[s][0], wd2[0],
                      fma2(*(const u64*)&sx[s][2], wd2[1],
                      mul2(*(const u64*)&sx[s][4], wd2[2])));
            float svlo, svhi; unpk2(sv2, svlo, svhi);
            float sv = svlo + svhi + bdt;
            float delta, f;
            delta_f(sv, delta, f);
            S += delta;
            float du = delta * uu;
#pragma unroll
            for (int n = 0; n < NS; n++) {
                float dA = __expf(delta * A[n]);
                h[n] = h[n] * dA + du * sx[s][6 + n];
            }
        }
#pragma unroll
        for (int j = 0; j < 8; j++) h2[j] = pk2(h[2 * j], h[2 * j + 1]);
    }

    size_t base = ((((size_t)(b * KD + k)) * NCH + c) * DD + d) * NS;
#pragma unroll
    for (int n = 0; n < NS; n++) g_P[base + n] = __expf(A[n] * S);
#pragma unroll
    for (int j = 0; j < 8; j++) *(u64*)&g_hend[base + 2 * j] = h2[j];
}

// ---------------- scan phase 2: stitch chunk boundaries ----------------
__global__ void scan_p2() {
    int gid = blockIdx.x * blockDim.x + threadIdx.x;   // B*K*D*N = 24576
    int dn = gid % (DD * NS);
    int k = (gid / (DD * NS)) % KD;
    int b = gid / (DD * NS * KD);
    float h = 0.f;
    size_t stride = (size_t)DD * NS;
    size_t base = ((size_t)(b * KD + k)) * NCH * stride + dn;
    for (int c = 0; c < NCH; c++) {
        size_t idx = base + (size_t)c * stride;
        float Pv = g_P[idx];
        float he = g_hend[idx];
        g_P[idx] = h;
        h = Pv * h + he;
    }
}

// ---------------- scan phase 3: full scan, emit y ----------------
__global__ void __launch_bounds__(DD) scan_p3(const float* __restrict__ dtw,
                                              const float* __restrict__ dtb,
                                              const float* __restrict__ Alogs,
                                              const float* __restrict__ Ds) {
    int blk = blockIdx.x;
    int c = blk % NCH;
    int k = (blk / NCH) % KD;
    int b = blk / (NCH * KD);
    int d = threadIdx.x;

    u64 wd2[3];
#pragma unroll
    for (int r = 0; r < 3; r++)
        wd2[r] = pk2(dtw[(k * DD + d) * RR + 2 * r], dtw[(k * DD + d) * RR + 2 * r + 1]);
    float bdt = dtb[k * DD + d];
    float Dsv = Ds[k * DD + d];
    float A[NS];
    bool powok = true;
#pragma unroll
    for (int n = 0; n < NS; n++) {
        float an = __expf(Alogs[(k * DD + d) * NS + n]);
        A[n] = -an;
        powok = powok && (fabsf(an - (float)(n + 1)) < 1e-3f * (float)(n + 1));
    }

    int p0, pstep;
    scan_affine(k, c, p0, pstep);

    __shared__ __align__(16) float sx[CHL][40];
    for (int i = d; i < CHL * 38; i += DD) {
        int s = i / 38, cc = i - s * 38;
        sx[s][cc] = g_xdbl[((size_t)(b * LS + p0 + s * pstep)) * XD + k * 38 + cc];
    }
    __syncthreads();

    size_t base = ((((size_t)(b * KD + k)) * NCH + c) * DD + d) * NS;
    const float* up = g_u + ((size_t)(b * LS + p0)) * DD + d;
    int ustep = pstep * DD;
    float* oyp = g_oy + (((size_t)(b * KD + k)) * LS + c * CHL) * DD + d;

    if (powok) {
        u64 h2[8];
#pragma unroll
        for (int j = 0; j < 8; j++) h2[j] = *(const u64*)&g_P[base + 2 * j];
        for (int s = 0; s < CHL; s++) {
            float uu = *up; up += ustep;
            u64 sv2 = fma2(*(const u64*)&sx[s][0], wd2[0],
                      fma2(*(const u64*)&sx[s][2], wd2[1],
                      mul2(*(const u64*)&sx[s][4], wd2[2])));
            float svlo, svhi; unpk2(sv2, svlo, svhi);
            float sv = svlo + svhi + bdt;
            float delta, f;
            delta_f(sv, delta, f);
            u64 q[8];
            pow_tree(f, q);
            u64 dud = dup2(delta * uu);
            u64 y2 = 0ull;
#pragma unroll
            for (int j = 0; j < 8; j++) {
                u64 Bp = *(const u64*)&sx[s][6 + 2 * j];
                u64 Cp = *(const u64*)&sx[s][22 + 2 * j];
                h2[j] = fma2(h2[j], q[j], mul2(dud, Bp));
                y2 = fma2(h2[j], Cp, y2);
            }
            float ylo, yhi;
            unpk2(y2, ylo, yhi);
            *oyp = ylo + yhi + uu * Dsv;
            oyp += DD;
        }
    } else {
        float h[NS];
#pragma unroll
        for (int n = 0; n < NS; n++) h[n] = g_P[base + n];
        for (int s = 0; s < CHL; s++) {
            float uu = *up; up += ustep;
            u64 sv2 = fma2(*(const u64*)&sx[s][0], wd2[0],
                      fma2(*(const u64*)&sx[s][2], wd2[1],
                      mul2(*(const u64*)&sx[s][4], wd2[2])));
            float svlo, svhi; unpk2(sv2, svlo, svhi);
            float sv = svlo + svhi + bdt;
            float delta, f;
            delta_f(sv, delta, f);
            float du = delta * uu;
            float y = 0.f;
#pragma unroll
            for (int n = 0; n < NS; n++) {
                float dA = __expf(delta * A[n]);
                h[n] = h[n] * dA + du * sx[s][6 + n];
                y += h[n] * sx[s][22 + n];
            }
            *oyp = y + uu * Dsv;
            oyp += DD;
        }
    }
}

// ---------------- combine 4 directions + LN(out_norm) + silu(z) gate -------------
__global__ void combine_ln_silu(const float* __restrict__ gno, const float* __restrict__ bno) {
    int warp = (blockIdx.x * blockDim.x + threadIdx.x) >> 5;
    int lane = threadIdx.x & 31;
    if (warp >= MPIX) return;
    int b = warp / LS, p = warp - b * LS;
    int hh = p / WW, ww = p - hh * WW;
    int tcol = ww * HH + hh;

    size_t base0 = (((size_t)(b * KD + 0)) * LS + p) * DD;
    size_t base1 = (((size_t)(b * KD + 1)) * LS + tcol) * DD;
    size_t base2 = (((size_t)(b * KD + 2)) * LS + (LS - 1 - p)) * DD;
    size_t base3 = (((size_t)(b * KD + 3)) * LS + (LS - 1 - tcol)) * DD;

    float v[6], s = 0.f, ss = 0.f;
#pragma unroll
    for (int j = 0; j < 6; j++) {
        int dd = lane + j * 32;
        float t = g_oy[base0 + dd] + g_oy[base1 + dd] + g_oy[base2 + dd] + g_oy[base3 + dd];
        v[j] = t; s += t; ss += t * t;
    }
#pragma unroll
    for (int o = 16; o > 0; o >>= 1) { s += __shfl_xor_sync(~0u, s, o); ss += __shfl_xor_sync(~0u, ss, o); }
    float m = s * (1.f / DD);
    float var = ss * (1.f / DD) - m * m;
    float inv = rsqrtf(var + 1e-5f);
#pragma unroll
    for (int j = 0; j < 6; j++) {
        int dd = lane + j * 32;
        float z = g_xz[((size_t)warp) * (2 * DD) + DD + dd];
        float yn = (v[j] - m) * inv * gno[dd] + bno[dd];
        g_ypost[(size_t)warp * DD + dd] = yn * siluf(z);
    }
}

// ---------------- residual 1 + LN_ffn ----------------
__global__ void resid1_lnffn(const float* __restrict__ x, const float* __restrict__ scale1,
                             const float* __restrict__ gf, const float* __restrict__ bf) {
    int warp = (blockIdx.x * blockDim.x + threadIdx.x) >> 5;
    int lane = threadIdx.x & 31;
    if (warp >= MPIX) return;
    int b = warp / LS, p = warp - b * LS;
    float v[3], s = 0.f, ss = 0.f;
#pragma unroll
    for (int j = 0; j < 3; j++) {
        int c = lane + j * 32;
        float t = g_t96[(size_t)warp * CC + c] + x[((size_t)(b * CC + c)) * LS + p] * scale1[c];
        v[j] = t; s += t; ss += t * t;
        g_x2[(size_t)warp * CC + c] = t;
    }
#pragma unroll
    for (int o = 16; o > 0; o >>= 1) { s += __shfl_xor_sync(~0u, s, o); ss += __shfl_xor_sync(~0u, ss, o); }
    float m = s * (1.f / CC);
    float var = ss * (1.f / CC) - m * m;
    float inv = rsqrtf(var + 1e-5f);
#pragma unroll
    for (int j = 0; j < 3; j++) {
        int c = lane + j * 32;
        g_h1n[(size_t)warp * CC + c] = (v[j] - m) * inv * gf[c] + bf[c];
    }
}

// ---------------- final: residual 2 + tiled transpose to (B,C,H,W) ----------------
__global__ void __launch_bounds__(256) final_kernel(const float* __restrict__ scale2,
                                                    float* __restrict__ out) {
    __shared__ float tile[CC][33];
    int b = blockIdx.y;
    int p0 = blockIdx.x * 32;
    int t = threadIdx.x;
    for (int idx = t; idx < 32 * CC; idx += 256) {
        int i = idx / CC;
        int c = idx - i * CC;
        size_t src = ((size_t)(b * LS + p0 + i)) * CC + c;
        tile[c][i] = g_t96[src] + g_x2[src] * scale2[c];
    }
    __syncthreads();
    for (int idx = t; idx < 32 * CC; idx += 256) {
        int c = idx >> 5;
        int i = idx & 31;
        out[((size_t)(b * CC + c)) * LS + p0 + i] = tile[c][i];
    }
}

// ---------------- launch ----------------
extern "C" void kernel_launch(void* const* d_in, const int* in_sizes, int n_in,
                              void* d_out, int out_size) {
    const float* x          = (const float*)d_in[0];
    const float* ln_in_g    = (const float*)d_in[1];
    const float* ln_in_b    = (const float*)d_in[2];
    const float* in_proj_w  = (const float*)d_in[3];
    const float* in_proj_b  = (const float*)d_in[4];
    const float* conv_w     = (const float*)d_in[5];
    const float* conv_b     = (const float*)d_in[6];
    const float* x_proj_w   = (const float*)d_in[7];
    const float* dt_w       = (const float*)d_in[8];
    const float* dt_b       = (const float*)d_in[9];
    const float* A_logs     = (const float*)d_in[10];
    const float* Ds         = (const float*)d_in[11];
    const float* out_norm_g = (const float*)d_in[12];
    const float* out_norm_b = (const float*)d_in[13];
    const float* out_proj_w = (const float*)d_in[14];
    const float* out_proj_b = (const float*)d_in[15];
    const float* ln_ffn_g   = (const float*)d_in[16];
    const float* ln_ffn_b   = (const float*)d_in[17];
    const float* fc1_w      = (const float*)d_in[18];
    const float* fc1_b      = (const float*)d_in[19];
    const float* fc2_w      = (const float*)d_in[20];
    const float* fc2_b      = (const float*)d_in[21];
    const float* scale1     = (const float*)d_in[22];
    const float* scale2     = (const float*)d_in[23];

    float *p_xz, *p_u, *p_xdbl, *p_ypost, *p_t96, *p_h1n, *p_t192;
    cudaGetSymbolAddress((void**)&p_xz,    g_xz);
    cudaGetSymbolAddress((void**)&p_u,     g_u);
    cudaGetSymbolAddress((void**)&p_xdbl,  g_xdbl);
    cudaGetSymbolAddress((void**)&p_ypost, g_ypost);
    cudaGetSymbolAddress((void**)&p_t96,   g_t96);
    cudaGetSymbolAddress((void**)&p_h1n,   g_h1n);
    cudaGetSymbolAddress((void**)&p_t192,  g_t192);

    // 1. fused LN + in_proj: x (NCHW) -> g_xz (B,L,384)
    gemm_ln_in<<<dim3((2 * DD) / 64, MPIX / 128), 256>>>(x, ln_in_g, ln_in_b, in_proj_w, in_proj_b, p_xz);
    // 2. depthwise conv 3x3 + SiLU
    conv_silu_kernel<<<MPIX, DD>>>(conv_w, conv_b);
    // 3. x_proj: (M,192)x(152,192)^T
    gemm2<0><<<dim3(3, MPIX / 128), 256>>>(p_u, x_proj_w, nullptr, p_xdbl, MPIX, XD, DD);
    // 4-6. chunked selective scan
    scan_p1<<<BSZ * KD * NCH, DD>>>(dt_w, dt_b, A_logs);
    scan_p2<<<(BSZ * KD * DD * NS) / 256, 256>>>();
    scan_p3<<<BSZ * KD * NCH, DD>>>(dt_w, dt_b, A_logs, Ds);
    // 7. combine + LN + gate
    combine_ln_silu<<<MPIX / 8, 256>>>(out_norm_g, out_norm_b);
    // 8. out_proj: (M,192)x(96,192)^T
    gemm2<0><<<dim3(2, MPIX / 128), 256>>>(p_ypost, out_proj_w, out_proj_b, p_t96, MPIX, CC, DD);
    // 9. residual1 + LN_ffn
    resid1_lnffn<<<MPIX / 8, 256>>>(x, scale1, ln_ffn_g, ln_ffn_b);
    // 10. fc1 + leaky relu
    gemm2<1><<<dim3(3, MPIX / 128), 256>>>(p_h1n, fc1_w, fc1_b, p_t192, MPIX, DD, CC);
    // 11. fc2
    gemm2<0><<<dim3(2, MPIX / 128), 256>>>(p_t192, fc2_w, fc2_b, p_t96, MPIX, CC, DD);
    // 12. residual2 + transpose to (B,C,H,W)
    final_kernel<<<dim3(LS / 32, BSZ), 256>>>(scale2, (float*)d_out);
}

// round 14
// speedup vs baseline: 1.0101x; 1.0101x over previous
#include <cuda_runtime.h>
#include <math.h>
#include <stdint.h>
#include <stddef.h>

// ---------------- problem constants ----------------
#define BSZ 2
#define HH 96
#define WW 96
#define LS 9216          // H*W
#define CC 96            // d_model
#define DD 192           // d_inner
#define NS 16            // d_state
#define KD 4             // K directions
#define RR 6             // dt_rank
#define XD 152           // stacked x_proj output dim
#define NCH 96           // number of chunks
#define CHL 96           // chunk length
#define MPIX (BSZ*LS)    // 18432

typedef unsigned long long u64;

// ---------------- scratch ----------------
__device__ float g_xn   [BSZ*LS*CC];
__device__ float g_xz   [BSZ*LS*2*DD];
__device__ float g_u    [BSZ*LS*DD];
__device__ float g_xdbl [BSZ*LS*XD];
__device__ float g_P    [BSZ*KD*NCH*DD*NS];
__device__ float g_hend [BSZ*KD*NCH*DD*NS];
__device__ float g_oy   [BSZ*KD*LS*DD];
__device__ float g_ypost[BSZ*LS*DD];
__device__ float g_t96  [BSZ*LS*CC];
__device__ float g_x2   [BSZ*LS*CC];
__device__ float g_h1n  [BSZ*LS*CC];
__device__ float g_t192 [BSZ*LS*DD];

// ---------------- f32x2 packed helpers ----------------
__device__ __forceinline__ u64 pk2(float lo, float hi) {
    u64 r;
    asm("mov.b64 %0, {%1, %2};" : "=l"(r) : "r"(__float_as_uint(lo)), "r"(__float_as_uint(hi)));
    return r;
}
__device__ __forceinline__ u64 dup2(float v) {
    u64 r;
    asm("mov.b64 %0, {%1, %1};" : "=l"(r) : "r"(__float_as_uint(v)));
    return r;
}
__device__ __forceinline__ u64 fma2(u64 a, u64 b, u64 c) {
    u64 d;
    asm("fma.rn.f32x2 %0, %1, %2, %3;" : "=l"(d) : "l"(a), "l"(b), "l"(c));
    return d;
}
__device__ __forceinline__ u64 mul2(u64 a, u64 b) {
    u64 d;
    asm("mul.rn.f32x2 %0, %1, %2;" : "=l"(d) : "l"(a), "l"(b));
    return d;
}
__device__ __forceinline__ void unpk2(u64 v, float& lo, float& hi) {
    unsigned int a, b;
    asm("mov.b64 {%0, %1}, %2;" : "=r"(a), "=r"(b) : "l"(v));
    lo = __uint_as_float(a); hi = __uint_as_float(b);
}

// ---------------- math helpers ----------------
__device__ __forceinline__ float siluf(float x) {
    return x / (1.f + __expf(-x));
}
// affine scan-position: position p(s) = p0 + s*pstep (valid since CHL==HH==WW==96)
__device__ __forceinline__ void scan_affine(int k, int c, int& p0, int& pstep) {
    if (k == 0)      { p0 = c * 96;                pstep = 1;   }
    else if (k == 1) { p0 = c;                     pstep = 96;  }
    else if (k == 2) { p0 = (95 - c) * 96 + 95;    pstep = -1;  }
    else             { p0 = 95 * 96 + (95 - c);    pstep = -96; }
}
// sv -> (delta=softplus(sv), f=exp(-delta)) with one MUFU exp + log + rcp
__device__ __forceinline__ void delta_f(float sv, float& delta, float& f) {
    float e = __expf(-fabsf(sv));
    float opx = 1.f + e;
    delta = fmaxf(sv, 0.f) + __logf(opx);
    f = __fdividef((sv >= 0.f) ? e : 1.f, opx);
}
// powers (f^1..f^16) packed as 8 f32x2 via log-depth tree
__device__ __forceinline__ void pow_tree(float f, u64 q[8]) {
    float f2 = f * f, f4 = f2 * f2, f8 = f4 * f4;
    u64 d2 = dup2(f2), d4 = dup2(f4), d8 = dup2(f8);
    q[0] = pk2(f, f2);
    q[1] = mul2(q[0], d2);
    q[2] = mul2(q[0], d4);
    q[3] = mul2(q[1], d4);
    q[4] = mul2(q[0], d8);
    q[5] = mul2(q[1], d8);
    q[6] = mul2(q[2], d8);
    q[7] = mul2(q[3], d8);
}
// per-thread check: A_n == -(n+1)?
__device__ __forceinline__ bool check_powok(const float* Alogs, int k, int d) {
    bool ok = true;
#pragma unroll
    for (int n = 0; n < NS; n++) {
        float an = __expf(Alogs[(k * DD + d) * NS + n]);
        ok = ok && (fabsf(an - (float)(n + 1)) < 1e-3f * (float)(n + 1));
    }
    return ok;
}

// ---------------- LN over channels of NCHW -> (B,L,C) ----------------
__global__ void ln_in_kernel(const float* __restrict__ x,
                             const float* __restrict__ g, const float* __restrict__ bb) {
    int warp = (blockIdx.x * blockDim.x + threadIdx.x) >> 5;
    int lane = threadIdx.x & 31;
    if (warp >= MPIX) return;
    int b = warp / LS, p = warp - b * LS;
    float v[3], s = 0.f, ss = 0.f;
#pragma unroll
    for (int j = 0; j < 3; j++) {
        int c = lane + j * 32;
        v[j] = x[((size_t)(b * CC + c)) * LS + p];
        s += v[j]; ss += v[j] * v[j];
    }
#pragma unroll
    for (int o = 16; o > 0; o >>= 1) { s += __shfl_xor_sync(~0u, s, o); ss += __shfl_xor_sync(~0u, ss, o); }
    float m = s * (1.f / CC);
    float var = ss * (1.f / CC) - m * m;
    float inv = rsqrtf(var + 1e-6f);
#pragma unroll
    for (int j = 0; j < 3; j++) {
        int c = lane + j * 32;
        g_xn[(size_t)warp * CC + c] = (v[j] - m) * inv * g[c] + bb[c];
    }
}

// ================= f32x2 GEMM (dup'd W smem, conflict-free wp reads) ==============
// C[m,n] = act(sum_k A[m,k]*W[n,k] + bias[n]); M%128==0, K%16==0
template <int ACT>
__global__ void __launch_bounds__(256) gemm2(const float* __restrict__ A, const float* __restrict__ W,
                                             const float* __restrict__ bias, float* __restrict__ C,
                                             int M, int N, int K) {
    __shared__ __align__(16) float As[16][130];
    __shared__ __align__(16) u64   Ws2[16][66];
    int t = threadIdx.x;
    int bn = blockIdx.x * 64, bm = blockIdx.y * 128;
    int tx = t & 15, ty = t >> 4;
    int m0 = ty * 8;

    u64 acc[4][4];
#pragma unroll
    for (int i = 0; i < 4; i++)
#pragma unroll
        for (int j = 0; j < 4; j++) acc[i][j] = 0ull;

    int lrow = t >> 2, lc4 = t & 3;

    for (int k0 = 0; k0 < K; k0 += 16) {
#pragma unroll
        for (int r = 0; r < 2; r++) {
            int row = lrow + r * 64;
            float4 v = *(const float4*)&A[(size_t)(bm + row) * K + k0 + lc4 * 4];
            As[lc4 * 4 + 0][row] = v.x; As[lc4 * 4 + 1][row] = v.y;
            As[lc4 * 4 + 2][row] = v.z; As[lc4 * 4 + 3][row] = v.w;
        }
        {
            float4 v = make_float4(0.f, 0.f, 0.f, 0.f);
            if (bn + lrow < N) v = *(const float4*)&W[(size_t)(bn + lrow) * K + k0 + lc4 * 4];
            Ws2[lc4 * 4 + 0][lrow] = dup2(v.x);
            Ws2[lc4 * 4 + 1][lrow] = dup2(v.y);
            Ws2[lc4 * 4 + 2][lrow] = dup2(v.z);
            Ws2[lc4 * 4 + 3][lrow] = dup2(v.w);
        }
        __syncthreads();
#pragma unroll
        for (int kk = 0; kk < 16; kk++) {
            u64 a[4], wp[4];
#pragma unroll
            for (int i = 0; i < 4; i++) a[i] = *(const u64*)&As[kk][m0 + 2 * i];
#pragma unroll
            for (int j = 0; j < 4; j++) wp[j] = Ws2[kk][tx + 16 * j];
#pragma unroll
            for (int i = 0; i < 4; i++)
#pragma unroll
                for (int j = 0; j < 4; j++) acc[i][j] = fma2(a[i], wp[j], acc[i][j]);
        }
        __syncthreads();
    }
#pragma unroll
    for (int j = 0; j < 4; j++) {
        int n = bn + tx + 16 * j;
        if (n >= N) continue;
        float bv = bias ? bias[n] : 0.f;
#pragma unroll
        for (int i = 0; i < 4; i++) {
            float lo, hi;
            unpk2(acc[i][j], lo, hi);
            lo += bv; hi += bv;
            if (ACT == 1) {
                lo = lo >= 0.f ? lo : 0.01f * lo;
                hi = hi >= 0.f ? hi : 0.01f * hi;
            }
            int m = bm + m0 + 2 * i;
            C[(size_t)m * N + n] = lo;
            C[(size_t)(m + 1) * N + n] = hi;
        }
    }
}

// ---------------- depthwise 3x3 conv + bias + SiLU ----------------
__global__ void __launch_bounds__(DD) conv_silu_kernel(const float* __restrict__ cw,
                                                       const float* __restrict__ cb) {
    int blk = blockIdx.x;
    int b = blk / LS, p = blk - b * LS;
    int d = threadIdx.x;
    int h = p / WW, w = p - h * WW;
    float acc = cb[d];
#pragma unroll
    for (int ky = 0; ky < 3; ky++) {
        int hh = h + ky - 1;
        if (hh < 0 || hh >= HH) continue;
#pragma unroll
        for (int kx = 0; kx < 3; kx++) {
            int ww2 = w + kx - 1;
            if (ww2 < 0 || ww2 >= WW) continue;
            acc += g_xz[((size_t)(b * LS + hh * WW + ww2)) * (2 * DD) + d] * cw[d * 9 + ky * 3 + kx];
        }
    }
    g_u[((size_t)(b * LS + p)) * DD + d] = siluf(acc);
}

// ================= scan phase 1 (FAST: A_n == -(n+1)) =================
__global__ void __launch_bounds__(192, 5) scan_p1_fast(const float* __restrict__ dtw,
                                                       const float* __restrict__ dtb,
                                                       const float* __restrict__ Alogs) {
    int blk = blockIdx.x;
    int c = blk % NCH;
    int k = (blk / NCH) % KD;
    int b = blk / (NCH * KD);
    int d = threadIdx.x;

    bool powok = check_powok(Alogs, k, d);

    u64 wd2[3];
#pragma unroll
    for (int r = 0; r < 3; r++)
        wd2[r] = pk2(dtw[(k * DD + d) * RR + 2 * r], dtw[(k * DD + d) * RR + 2 * r + 1]);
    float bdt = dtb[k * DD + d];

    int p0, pstep;
    scan_affine(k, c, p0, pstep);

    __shared__ __align__(16) float sx[CHL][40];
    for (int i = d; i < CHL * 38; i += DD) {
        int s = i / 38, cc = i - s * 38;
        sx[s][cc] = g_xdbl[((size_t)(b * LS + p0 + s * pstep)) * XD + k * 38 + cc];
    }
    __syncthreads();
    if (!powok) return;      // generic kernel handles this thread

    const float* up = g_u + ((size_t)(b * LS + p0)) * DD + d;
    int ustep = pstep * DD;
    float S = 0.f;
    u64 h2[8];
#pragma unroll
    for (int j = 0; j < 8; j++) h2[j] = 0ull;

    for (int s = 0; s < CHL; s++) {
        float uu = *up; up += ustep;
        u64 sv2 = fma2(*(const u64*)&sx[s][0], wd2[0],
                  fma2(*(const u64*)&sx[s][2], wd2[1],
                  mul2(*(const u64*)&sx[s][4], wd2[2])));
        float svlo, svhi; unpk2(sv2, svlo, svhi);
        float sv = svlo + svhi + bdt;
        float delta, f;
        delta_f(sv, delta, f);
        S += delta;
        u64 q[8];
        pow_tree(f, q);
        u64 dud = dup2(delta * uu);
#pragma unroll
        for (int j = 0; j < 8; j++) {
            u64 Bp = *(const u64*)&sx[s][6 + 2 * j];
            h2[j] = fma2(h2[j], q[j], mul2(dud, Bp));
        }
    }
    size_t base = ((((size_t)(b * KD + k)) * NCH + c) * DD + d) * NS;
    // chunk decay products: exp(A_n * S) = E^(n+1) with E = exp(-S)
    float E = __expf(-S);
    u64 qp[8];
    pow_tree(E, qp);
#pragma unroll
    for (int j = 0; j < 8; j++) *(u64*)&g_P[base + 2 * j] = qp[j];
#pragma unroll
    for (int j = 0; j < 8; j++) *(u64*)&g_hend[base + 2 * j] = h2[j];
}

// ================= scan phase 1 (GENERIC fallback, early-exits) =================
__global__ void __launch_bounds__(192) scan_p1_gen(const float* __restrict__ dtw,
                                                   const float* __restrict__ dtb,
                                                   const float* __restrict__ Alogs) {
    int blk = blockIdx.x;
    int c = blk % NCH;
    int k = (blk / NCH) % KD;
    int b = blk / (NCH * KD);
    int d = threadIdx.x;

    bool powok = check_powok(Alogs, k, d);
    if (__syncthreads_and(powok)) return;   // fast kernel covered everything

    float wdt[RR];
#pragma unroll
    for (int r = 0; r < RR; r++) wdt[r] = dtw[(k * DD + d) * RR + r];
    float bdt = dtb[k * DD + d];
    float A[NS];
#pragma unroll
    for (int n = 0; n < NS; n++) A[n] = -__expf(Alogs[(k * DD + d) * NS + n]);

    int p0, pstep;
    scan_affine(k, c, p0, pstep);

    __shared__ __align__(16) float sx[CHL][40];
    for (int i = d; i < CHL * 38; i += DD) {
        int s = i / 38, cc = i - s * 38;
        sx[s][cc] = g_xdbl[((size_t)(b * LS + p0 + s * pstep)) * XD + k * 38 + cc];
    }
    __syncthreads();
    if (powok) return;       // this thread already written by fast kernel

    const float* up = g_u + ((size_t)(b * LS + p0)) * DD + d;
    int ustep = pstep * DD;
    float S = 0.f;
    float h[NS];
#pragma unroll
    for (int n = 0; n < NS; n++) h[n] = 0.f;
    for (int s = 0; s < CHL; s++) {
        float uu = *up; up += ustep;
        float sv = bdt;
#pragma unroll
        for (int r = 0; r < RR; r++) sv += sx[s][r] * wdt[r];
        float e = __expf(-fabsf(sv));
        float delta = fmaxf(sv, 0.f) + log1pf(e);
        S += delta;
        float du = delta * uu;
#pragma unroll
        for (int n = 0; n < NS; n++) {
            float dA = __expf(delta * A[n]);
            h[n] = h[n] * dA + du * sx[s][6 + n];
        }
    }
    size_t base = ((((size_t)(b * KD + k)) * NCH + c) * DD + d) * NS;
#pragma unroll
    for (int n = 0; n < NS; n++) { g_P[base + n] = __expf(A[n] * S); g_hend[base + n] = h[n]; }
}

// ---------------- scan phase 2: stitch chunk boundaries ----------------
__global__ void scan_p2() {
    int gid = blockIdx.x * blockDim.x + threadIdx.x;   // B*K*D*N = 24576
    int dn = gid % (DD * NS);
    int k = (gid / (DD * NS)) % KD;
    int b = gid / (DD * NS * KD);
    float h = 0.f;
    size_t stride = (size_t)DD * NS;
    size_t base = ((size_t)(b * KD + k)) * NCH * stride + dn;
    for (int c = 0; c < NCH; c++) {
        size_t idx = base + (size_t)c * stride;
        float Pv = g_P[idx];
        float he = g_hend[idx];
        g_P[idx] = h;
        h = Pv * h + he;
    }
}

// ================= scan phase 3 (FAST) =================
__global__ void __launch_bounds__(192, 5) scan_p3_fast(const float* __restrict__ dtw,
                                                       const float* __restrict__ dtb,
                                                       const float* __restrict__ Alogs,
                                                       const float* __restrict__ Ds) {
    int blk = blockIdx.x;
    int c = blk % NCH;
    int k = (blk / NCH) % KD;
    int b = blk / (NCH * KD);
    int d = threadIdx.x;

    bool powok = check_powok(Alogs, k, d);

    u64 wd2[3];
#pragma unroll
    for (int r = 0; r < 3; r++)
        wd2[r] = pk2(dtw[(k * DD + d) * RR + 2 * r], dtw[(k * DD + d) * RR + 2 * r + 1]);
    float bdt = dtb[k * DD + d];
    float Dsv = Ds[k * DD + d];

    int p0, pstep;
    scan_affine(k, c, p0, pstep);

    __shared__ __align__(16) float sx[CHL][40];
    for (int i = d; i < CHL * 38; i += DD) {
        int s = i / 38, cc = i - s * 38;
        sx[s][cc] = g_xdbl[((size_t)(b * LS + p0 + s * pstep)) * XD + k * 38 + cc];
    }
    __syncthreads();
    if (!powok) return;

    size_t base = ((((size_t)(b * KD + k)) * NCH + c) * DD + d) * NS;
    const float* up = g_u + ((size_t)(b * LS + p0)) * DD + d;
    int ustep = pstep * DD;
    float* oyp = g_oy + (((size_t)(b * KD + k)) * LS + c * CHL) * DD + d;

    u64 h2[8];
#pragma unroll
    for (int j = 0; j < 8; j++) h2[j] = *(const u64*)&g_P[base + 2 * j];
    for (int s = 0; s < CHL; s++) {
        float uu = *up; up += ustep;
        u64 sv2 = fma2(*(const u64*)&sx[s][0], wd2[0],
                  fma2(*(const u64*)&sx[s][2], wd2[1],
                  mul2(*(const u64*)&sx[s][4], wd2[2])));
        float svlo, svhi; unpk2(sv2, svlo, svhi);
        float sv = svlo + svhi + bdt;
        float delta, f;
        delta_f(sv, delta, f);
        u64 q[8];
        pow_tree(f, q);
        u64 dud = dup2(delta * uu);
        u64 y2 = 0ull;
#pragma unroll
        for (int j = 0; j < 8; j++) {
            u64 Bp = *(const u64*)&sx[s][6 + 2 * j];
            u64 Cp = *(const u64*)&sx[s][22 + 2 * j];
            h2[j] = fma2(h2[j], q[j], mul2(dud, Bp));
            y2 = fma2(h2[j], Cp, y2);
        }
        float ylo, yhi;
        unpk2(y2, ylo, yhi);
        *oyp = ylo + yhi + uu * Dsv;
        oyp += DD;
    }
}

// ================= scan phase 3 (GENERIC fallback, early-exits) =================
__global__ void __launch_bounds__(192) scan_p3_gen(const float* __restrict__ dtw,
                                                   const float* __restrict__ dtb,
                                                   const float* __restrict__ Alogs,
                                                   const float* __restrict__ Ds) {
    int blk = blockIdx.x;
    int c = blk % NCH;
    int k = (blk / NCH) % KD;
    int b = blk / (NCH * KD);
    int d = threadIdx.x;

    bool powok = check_powok(Alogs, k, d);
    if (__syncthreads_and(powok)) return;

    float wdt[RR];
#pragma unroll
    for (int r = 0; r < RR; r++) wdt[r] = dtw[(k * DD + d) * RR + r];
    float bdt = dtb[k * DD + d];
    float Dsv = Ds[k * DD + d];
    float A[NS];
#pragma unroll
    for (int n = 0; n < NS; n++) A[n] = -__expf(Alogs[(k * DD + d) * NS + n]);

    int p0, pstep;
    scan_affine(k, c, p0, pstep);

    __shared__ __align__(16) float sx[CHL][40];
    for (int i = d; i < CHL * 38; i += DD) {
        int s = i / 38, cc = i - s * 38;
        sx[s][cc] = g_xdbl[((size_t)(b * LS + p0 + s * pstep)) * XD + k * 38 + cc];
    }
    __syncthreads();
    if (powok) return;

    size_t base = ((((size_t)(b * KD + k)) * NCH + c) * DD + d) * NS;
    const float* up = g_u + ((size_t)(b * LS + p0)) * DD + d;
    int ustep = pstep * DD;
    float* oyp = g_oy + (((size_t)(b * KD + k)) * LS + c * CHL) * DD + d;

    float h[NS];
#pragma unroll
    for (int n = 0; n < NS; n++) h[n] = g_P[base + n];
    for (int s = 0; s < CHL; s++) {
        float uu = *up; up += ustep;
        float sv = bdt;
#pragma unroll
        for (int r = 0; r < RR; r++) sv += sx[s][r] * wdt[r];
        float e = __expf(-fabsf(sv));
        float delta = fmaxf(sv, 0.f) + log1pf(e);
        float du = delta * uu;
        float y = 0.f;
#pragma unroll
        for (int n = 0; n < NS; n++) {
            float dA = __expf(delta * A[n]);
            h[n] = h[n] * dA + du * sx[s][6 + n];
            y += h[n] * sx[s][22 + n];
        }
        *oyp = y + uu * Dsv;
        oyp += DD;
    }
}

// ---------------- combine 4 directions + LN(out_norm) + silu(z) gate -------------
__global__ void combine_ln_silu(const float* __restrict__ gno, const float* __restrict__ bno) {
    int warp = (blockIdx.x * blockDim.x + threadIdx.x) >> 5;
    int lane = threadIdx.x & 31;
    if (warp >= MPIX) return;
    int b = warp / LS, p = warp - b * LS;
    int hh = p / WW, ww = p - hh * WW;
    int tcol = ww * HH + hh;

    size_t base0 = (((size_t)(b * KD + 0)) * LS + p) * DD;
    size_t base1 = (((size_t)(b * KD + 1)) * LS + tcol) * DD;
    size_t base2 = (((size_t)(b * KD + 2)) * LS + (LS - 1 - p)) * DD;
    size_t base3 = (((size_t)(b * KD + 3)) * LS + (LS - 1 - tcol)) * DD;

    float v[6], s = 0.f, ss = 0.f;
#pragma unroll
    for (int j = 0; j < 6; j++) {
        int dd = lane + j * 32;
        float t = g_oy[base0 + dd] + g_oy[base1 + dd] + g_oy[base2 + dd] + g_oy[base3 + dd];
        v[j] = t; s += t; ss += t * t;
    }
#pragma unroll
    for (int o = 16; o > 0; o >>= 1) { s += __shfl_xor_sync(~0u, s, o); ss += __shfl_xor_sync(~0u, ss, o); }
    float m = s * (1.f / DD);
    float var = ss * (1.f / DD) - m * m;
    float inv = rsqrtf(var + 1e-5f);
#pragma unroll
    for (int j = 0; j < 6; j++) {
        int dd = lane + j * 32;
        float z = g_xz[((size_t)warp) * (2 * DD) + DD + dd];
        float yn = (v[j] - m) * inv * gno[dd] + bno[dd];
        g_ypost[(size_t)warp * DD + dd] = yn * siluf(z);
    }
}

// ---------------- residual 1 + LN_ffn ----------------
__global__ void resid1_lnffn(const float* __restrict__ x, const float* __restrict__ scale1,
                             const float* __restrict__ gf, const float* __restrict__ bf) {
    int warp = (blockIdx.x * blockDim.x + threadIdx.x) >> 5;
    int lane = threadIdx.x & 31;
    if (warp >= MPIX) return;
    int b = warp / LS, p = warp - b * LS;
    float v[3], s = 0.f, ss = 0.f;
#pragma unroll
    for (int j = 0; j < 3; j++) {
        int c = lane + j * 32;
        float t = g_t96[(size_t)warp * CC + c] + x[((size_t)(b * CC + c)) * LS + p] * scale1[c];
        v[j] = t; s += t; ss += t * t;
        g_x2[(size_t)warp * CC + c] = t;
    }
#pragma unroll
    for (int o = 16; o > 0; o >>= 1) { s += __shfl_xor_sync(~0u, s, o); ss += __shfl_xor_sync(~0u, ss, o); }
    float m = s * (1.f / CC);
    float var = ss * (1.f / CC) - m * m;
    float inv = rsqrtf(var + 1e-5f);
#pragma unroll
    for (int j = 0; j < 3; j++) {
        int c = lane + j * 32;
        g_h1n[(size_t)warp * CC + c] = (v[j] - m) * inv * gf[c] + bf[c];
    }
}

// ---------------- final: residual 2 + tiled transpose to (B,C,H,W) ----------------
__global__ void __launch_bounds__(256) final_kernel(const float* __restrict__ scale2,
                                                    float* __restrict__ out) {
    __shared__ float tile[CC][33];
    int b = blockIdx.y;
    int p0 = blockIdx.x * 32;
    int t = threadIdx.x;
    for (int idx = t; idx < 32 * CC; idx += 256) {
        int i = idx / CC;
        int c = idx - i * CC;
        size_t src = ((size_t)(b * LS + p0 + i)) * CC + c;
        tile[c][i] = g_t96[src] + g_x2[src] * scale2[c];
    }
    __syncthreads();
    for (int idx = t; idx < 32 * CC; idx += 256) {
        int c = idx >> 5;
        int i = idx & 31;
        out[((size_t)(b * CC + c)) * LS + p0 + i] = tile[c][i];
    }
}

// ---------------- launch ----------------
extern "C" void kernel_launch(void* const* d_in, const int* in_sizes, int n_in,
                              void* d_out, int out_size) {
    const float* x          = (const float*)d_in[0];
    const float* ln_in_g    = (const float*)d_in[1];
    const float* ln_in_b    = (const float*)d_in[2];
    const float* in_proj_w  = (const float*)d_in[3];
    const float* in_proj_b  = (const float*)d_in[4];
    const float* conv_w     = (const float*)d_in[5];
    const float* conv_b     = (const float*)d_in[6];
    const float* x_proj_w   = (const float*)d_in[7];
    const float* dt_w       = (const float*)d_in[8];
    const float* dt_b       = (const float*)d_in[9];
    const float* A_logs     = (const float*)d_in[10];
    const float* Ds         = (const float*)d_in[11];
    const float* out_norm_g = (const float*)d_in[12];
    const float* out_norm_b = (const float*)d_in[13];
    const float* out_proj_w = (const float*)d_in[14];
    const float* out_proj_b = (const float*)d_in[15];
    const float* ln_ffn_g   = (const float*)d_in[16];
    const float* ln_ffn_b   = (const float*)d_in[17];
    const float* fc1_w      = (const float*)d_in[18];
    const float* fc1_b      = (const float*)d_in[19];
    const float* fc2_w      = (const float*)d_in[20];
    const float* fc2_b      = (const float*)d_in[21];
    const float* scale1     = (const float*)d_in[22];
    const float* scale2     = (const float*)d_in[23];

    float *p_xn, *p_xz, *p_u, *p_xdbl, *p_ypost, *p_t96, *p_h1n, *p_t192;
    cudaGetSymbolAddress((void**)&p_xn,    g_xn);
    cudaGetSymbolAddress((void**)&p_xz,    g_xz);
    cudaGetSymbolAddress((void**)&p_u,     g_u);
    cudaGetSymbolAddress((void**)&p_xdbl,  g_xdbl);
    cudaGetSymbolAddress((void**)&p_ypost, g_ypost);
    cudaGetSymbolAddress((void**)&p_t96,   g_t96);
    cudaGetSymbolAddress((void**)&p_h1n,   g_h1n);
    cudaGetSymbolAddress((void**)&p_t192,  g_t192);

    // 1. LN over channels -> g_xn (B,L,C)
    ln_in_kernel<<<MPIX / 8, 256>>>(x, ln_in_g, ln_in_b);
    // 2. in_proj: (M,96)x(384,96)^T
    gemm2<0><<<dim3(384 / 64, MPIX / 128), 256>>>(p_xn, in_proj_w, in_proj_b, p_xz, MPIX, 2 * DD, CC);
    // 3. depthwise conv 3x3 + SiLU
    conv_silu_kernel<<<MPIX, DD>>>(conv_w, conv_b);
    // 4. x_proj: (M,192)x(152,192)^T
    gemm2<0><<<dim3(3, MPIX / 128), 256>>>(p_u, x_proj_w, nullptr, p_xdbl, MPIX, XD, DD);
    // 5-7. chunked selective scan (fast + generic-fallback pairs)
    scan_p1_fast<<<BSZ * KD * NCH, DD>>>(dt_w, dt_b, A_logs);
    scan_p1_gen <<<BSZ * KD * NCH, DD>>>(dt_w, dt_b, A_logs);
    scan_p2<<<(BSZ * KD * DD * NS) / 256, 256>>>();
    scan_p3_fast<<<BSZ * KD * NCH, DD>>>(dt_w, dt_b, A_logs, Ds);
    scan_p3_gen <<<BSZ * KD * NCH, DD>>>(dt_w, dt_b, A_logs, Ds);
    // 8. combine + LN + gate
    combine_ln_silu<<<MPIX / 8, 256>>>(out_norm_g, out_norm_b);
    // 9. out_proj: (M,192)x(96,192)^T
    gemm2<0><<<dim3(2, MPIX / 128), 256>>>(p_ypost, out_proj_w, out_proj_b, p_t96, MPIX, CC, DD);
    // 10. residual1 + LN_ffn
    resid1_lnffn<<<MPIX / 8, 256>>>(x, scale1, ln_ffn_g, ln_ffn_b);
    // 11. fc1 + leaky relu
    gemm2<1><<<dim3(3, MPIX / 128), 256>>>(p_h1n, fc1_w, fc1_b, p_t192, MPIX, DD, CC);
    // 12. fc2
    gemm2<0><<<dim3(2, MPIX / 128), 256>>>(p_t192, fc2_w, fc2_b, p_t96, MPIX, CC, DD);
    // 13. residual2 + transpose to (B,C,H,W)
    final_kernel<<<dim3(LS / 32, BSZ), 256>>>(scale2, (float*)d_out);
}

// round 15
// speedup vs baseline: 1.2820x; 1.2692x over previous
#include <cuda_runtime.h>
#include <math.h>
#include <stdint.h>
#include <stddef.h>

// ---------------- problem constants ----------------
#define BSZ 2
#define HH 96
#define WW 96
#define LS 9216          // H*W
#define CC 96            // d_model
#define DD 192           // d_inner
#define NS 16            // d_state
#define KD 4             // K directions
#define RR 6             // dt_rank
#define XD 152           // stacked x_proj output dim
#define NCH 96           // number of chunks
#define CHL 96           // chunk length
#define MPIX (BSZ*LS)    // 18432

typedef unsigned long long u64;

// ---------------- scratch ----------------
__device__ float g_xn   [BSZ*LS*CC];
__device__ float g_xz   [BSZ*LS*2*DD];
__device__ float g_u    [BSZ*LS*DD];
__device__ float g_xdbl [BSZ*LS*XD];
__device__ float g_P    [BSZ*KD*NCH*DD*NS];
__device__ float g_hend [BSZ*KD*NCH*DD*NS];
__device__ float g_oy   [BSZ*KD*LS*DD];
__device__ float g_ypost[BSZ*LS*DD];
__device__ float g_t96  [BSZ*LS*CC];
__device__ float g_x2   [BSZ*LS*CC];
__device__ float g_h1n  [BSZ*LS*CC];
__device__ float g_t192 [BSZ*LS*DD];

// ---------------- f32x2 packed helpers ----------------
__device__ __forceinline__ u64 pk2(float lo, float hi) {
    u64 r;
    asm("mov.b64 %0, {%1, %2};" : "=l"(r) : "r"(__float_as_uint(lo)), "r"(__float_as_uint(hi)));
    return r;
}
__device__ __forceinline__ u64 dup2(float v) {
    u64 r;
    asm("mov.b64 %0, {%1, %1};" : "=l"(r) : "r"(__float_as_uint(v)));
    return r;
}
__device__ __forceinline__ u64 fma2(u64 a, u64 b, u64 c) {
    u64 d;
    asm("fma.rn.f32x2 %0, %1, %2, %3;" : "=l"(d) : "l"(a), "l"(b), "l"(c));
    return d;
}
__device__ __forceinline__ u64 mul2(u64 a, u64 b) {
    u64 d;
    asm("mul.rn.f32x2 %0, %1, %2;" : "=l"(d) : "l"(a), "l"(b));
    return d;
}
__device__ __forceinline__ void unpk2(u64 v, float& lo, float& hi) {
    unsigned int a, b;
    asm("mov.b64 {%0, %1}, %2;" : "=r"(a), "=r"(b) : "l"(v));
    lo = __uint_as_float(a); hi = __uint_as_float(b);
}

// ---------------- tf32 mma helpers ----------------
__device__ __forceinline__ uint32_t to_tf32(float f) {
    uint32_t u;
    asm("cvt.rna.tf32.f32 %0, %1;" : "=r"(u) : "f"(f));
    return u;
}
__device__ __forceinline__ void mma_tf32(float c[4], const uint32_t a[4], const uint32_t b[2]) {
    asm volatile("mma.sync.aligned.m16n8k8.row.col.f32.tf32.tf32.f32 "
                 "{%0,%1,%2,%3}, {%4,%5,%6,%7}, {%8,%9}, {%0,%1,%2,%3};"
                 : "+f"(c[0]), "+f"(c[1]), "+f"(c[2]), "+f"(c[3])
                 : "r"(a[0]), "r"(a[1]), "r"(a[2]), "r"(a[3]), "r"(b[0]), "r"(b[1]));
}

// ---------------- math helpers ----------------
__device__ __forceinline__ float siluf(float x) {
    return x / (1.f + __expf(-x));
}
__device__ __forceinline__ void scan_affine(int k, int c, int& p0, int& pstep) {
    if (k == 0)      { p0 = c * 96;                pstep = 1;   }
    else if (k == 1) { p0 = c;                     pstep = 96;  }
    else if (k == 2) { p0 = (95 - c) * 96 + 95;    pstep = -1;  }
    else             { p0 = 95 * 96 + (95 - c);    pstep = -96; }
}
__device__ __forceinline__ void delta_f(float sv, float& delta, float& f) {
    float e = __expf(-fabsf(sv));
    float opx = 1.f + e;
    delta = fmaxf(sv, 0.f) + __logf(opx);
    f = __fdividef((sv >= 0.f) ? e : 1.f, opx);
}
__device__ __forceinline__ void pow_tree(float f, u64 q[8]) {
    float f2 = f * f, f4 = f2 * f2, f8 = f4 * f4;
    u64 d2 = dup2(f2), d4 = dup2(f4), d8 = dup2(f8);
    q[0] = pk2(f, f2);
    q[1] = mul2(q[0], d2);
    q[2] = mul2(q[0], d4);
    q[3] = mul2(q[1], d4);
    q[4] = mul2(q[0], d8);
    q[5] = mul2(q[1], d8);
    q[6] = mul2(q[2], d8);
    q[7] = mul2(q[3], d8);
}
__device__ __forceinline__ bool check_powok(const float* Alogs, int k, int d) {
    bool ok = true;
#pragma unroll
    for (int n = 0; n < NS; n++) {
        float an = __expf(Alogs[(k * DD + d) * NS + n]);
        ok = ok && (fabsf(an - (float)(n + 1)) < 1e-3f * (float)(n + 1));
    }
    return ok;
}

// ---------------- LN over channels of NCHW -> (B,L,C) ----------------
__global__ void ln_in_kernel(const float* __restrict__ x,
                             const float* __restrict__ g, const float* __restrict__ bb) {
    int warp = (blockIdx.x * blockDim.x + threadIdx.x) >> 5;
    int lane = threadIdx.x & 31;
    if (warp >= MPIX) return;
    int b = warp / LS, p = warp - b * LS;
    float v[3], s = 0.f, ss = 0.f;
#pragma unroll
    for (int j = 0; j < 3; j++) {
        int c = lane + j * 32;
        v[j] = x[((size_t)(b * CC + c)) * LS + p];
        s += v[j]; ss += v[j] * v[j];
    }
#pragma unroll
    for (int o = 16; o > 0; o >>= 1) { s += __shfl_xor_sync(~0u, s, o); ss += __shfl_xor_sync(~0u, ss, o); }
    float m = s * (1.f / CC);
    float var = ss * (1.f / CC) - m * m;
    float inv = rsqrtf(var + 1e-6f);
#pragma unroll
    for (int j = 0; j < 3; j++) {
        int c = lane + j * 32;
        g_xn[(size_t)warp * CC + c] = (v[j] - m) * inv * g[c] + bb[c];
    }
}

// ================= tf32 tensor-core GEMM =================
// C[m,n] = act(sum_k A[m,k]*W[n,k] + bias[n]); M%128==0, K%32==0, N even
// block tile 128(M) x 32(N), 8 warps: warp = (wm 0..3)x(wn 0..1), warp tile 32x16
template <int ACT>
__global__ void __launch_bounds__(256) gemm_tc(const float* __restrict__ A,
                                               const float* __restrict__ W,
                                               const float* __restrict__ bias,
                                               float* __restrict__ C,
                                               int M, int N, int K) {
    __shared__ __align__(16) uint32_t Asm[128][36];  // A tile (tf32 bits), pad 36
    __shared__ __align__(16) uint32_t Wsn[32][36];   // W tile (tf32 bits), pad 36
    int t = threadIdx.x;
    int bn = blockIdx.x * 32, bm = blockIdx.y * 128;
    int warp = t >> 5, lane = t & 31;
    int wm = (warp >> 1) * 32, wn = (warp & 1) * 16;
    int lr = lane >> 2, lc = lane & 3;

    float acc[2][2][4];
#pragma unroll
    for (int mt = 0; mt < 2; mt++)
#pragma unroll
        for (int nt = 0; nt < 2; nt++)
#pragma unroll
            for (int r = 0; r < 4; r++) acc[mt][nt][r] = 0.f;

    for (int k0 = 0; k0 < K; k0 += 32) {
        // stage A: 128 rows x 32 k (coalesced float4 loads, conflict-light STS.128)
#pragma unroll
        for (int rep = 0; rep < 4; rep++) {
            int slot = t + rep * 256;          // 0..1023
            int m = slot >> 3, kq = slot & 7;
            float4 v = *(const float4*)&A[(size_t)(bm + m) * K + k0 + kq * 4];
            uint4 u = make_uint4(to_tf32(v.x), to_tf32(v.y), to_tf32(v.z), to_tf32(v.w));
            *(uint4*)&Asm[m][kq * 4] = u;
        }
        // stage W: 32 rows x 32 k (zero-fill rows past N)
        {
            int n = t >> 3, kq = t & 7;
            float4 v = make_float4(0.f, 0.f, 0.f, 0.f);
            if (bn + n < N) v = *(const float4*)&W[(size_t)(bn + n) * K + k0 + kq * 4];
            uint4 u = make_uint4(to_tf32(v.x), to_tf32(v.y), to_tf32(v.z), to_tf32(v.w));
            *(uint4*)&Wsn[n][kq * 4] = u;
        }
        __syncthreads();
#pragma unroll
        for (int ks = 0; ks < 32; ks += 8) {
            uint32_t a[2][4], b[2][2];
#pragma unroll
            for (int mt = 0; mt < 2; mt++) {
                int mb = wm + mt * 16;
                a[mt][0] = Asm[mb + lr][ks + lc];
                a[mt][1] = Asm[mb + 8 + lr][ks + lc];
                a[mt][2] = Asm[mb + lr][ks + 4 + lc];
                a[mt][3] = Asm[mb + 8 + lr][ks + 4 + lc];
            }
#pragma unroll
            for (int nt = 0; nt < 2; nt++) {
                int nb = wn + nt * 8;
                b[nt][0] = Wsn[nb + lr][ks + lc];
                b[nt][1] = Wsn[nb + lr][ks + 4 + lc];
            }
#pragma unroll
            for (int mt = 0; mt < 2; mt++)
#pragma unroll
                for (int nt = 0; nt < 2; nt++)
                    mma_tf32(acc[mt][nt], a[mt], b[nt]);
        }
        __syncthreads();
    }
    // epilogue: c0,c1 -> (row, 2lc), (row, 2lc+1); c2,c3 -> row+8
#pragma unroll
    for (int nt = 0; nt < 2; nt++) {
        int n = bn + wn + nt * 8 + 2 * lc;
        if (n >= N) continue;
        float bv0 = bias ? bias[n] : 0.f;
        float bv1 = bias ? bias[n + 1] : 0.f;
#pragma unroll
        for (int mt = 0; mt < 2; mt++) {
            int row0 = bm + wm + mt * 16 + lr;
            float v0 = acc[mt][nt][0] + bv0, v1 = acc[mt][nt][1] + bv1;
            float v2 = acc[mt][nt][2] + bv0, v3 = acc[mt][nt][3] + bv1;
            if (ACT == 1) {
                v0 = v0 >= 0.f ? v0 : 0.01f * v0;
                v1 = v1 >= 0.f ? v1 : 0.01f * v1;
                v2 = v2 >= 0.f ? v2 : 0.01f * v2;
                v3 = v3 >= 0.f ? v3 : 0.01f * v3;
            }
            *(float2*)&C[(size_t)row0 * N + n] = make_float2(v0, v1);
            *(float2*)&C[(size_t)(row0 + 8) * N + n] = make_float2(v2, v3);
        }
    }
}

// ---------------- depthwise 3x3 conv + bias + SiLU ----------------
__global__ void __launch_bounds__(DD) conv_silu_kernel(const float* __restrict__ cw,
                                                       const float* __restrict__ cb) {
    int blk = blockIdx.x;
    int b = blk / LS, p = blk - b * LS;
    int d = threadIdx.x;
    int h = p / WW, w = p - h * WW;
    float acc = cb[d];
#pragma unroll
    for (int ky = 0; ky < 3; ky++) {
        int hh = h + ky - 1;
        if (hh < 0 || hh >= HH) continue;
#pragma unroll
        for (int kx = 0; kx < 3; kx++) {
            int ww2 = w + kx - 1;
            if (ww2 < 0 || ww2 >= WW) continue;
            acc += g_xz[((size_t)(b * LS + hh * WW + ww2)) * (2 * DD) + d] * cw[d * 9 + ky * 3 + kx];
        }
    }
    g_u[((size_t)(b * LS + p)) * DD + d] = siluf(acc);
}

// ================= scan phase 1 (FAST: A_n == -(n+1)) =================
__global__ void __launch_bounds__(192, 5) scan_p1_fast(const float* __restrict__ dtw,
                                                       const float* __restrict__ dtb,
                                                       const float* __restrict__ Alogs) {
    int blk = blockIdx.x;
    int c = blk % NCH;
    int k = (blk / NCH) % KD;
    int b = blk / (NCH * KD);
    int d = threadIdx.x;

    bool powok = check_powok(Alogs, k, d);

    u64 wd2[3];
#pragma unroll
    for (int r = 0; r < 3; r++)
        wd2[r] = pk2(dtw[(k * DD + d) * RR + 2 * r], dtw[(k * DD + d) * RR + 2 * r + 1]);
    float bdt = dtb[k * DD + d];

    int p0, pstep;
    scan_affine(k, c, p0, pstep);

    __shared__ __align__(16) float sx[CHL][40];
    for (int i = d; i < CHL * 38; i += DD) {
        int s = i / 38, cc = i - s * 38;
        sx[s][cc] = g_xdbl[((size_t)(b * LS + p0 + s * pstep)) * XD + k * 38 + cc];
    }
    __syncthreads();
    if (!powok) return;

    const float* up = g_u + ((size_t)(b * LS + p0)) * DD + d;
    int ustep = pstep * DD;
    float S = 0.f;
    u64 h2[8];
#pragma unroll
    for (int j = 0; j < 8; j++) h2[j] = 0ull;

    for (int s = 0; s < CHL; s++) {
        float uu = *up; up += ustep;
        u64 sv2 = fma2(*(const u64*)&sx[s][0], wd2[0],
                  fma2(*(const u64*)&sx[s][2], wd2[1],
                  mul2(*(const u64*)&sx[s][4], wd2[2])));
        float svlo, svhi; unpk2(sv2, svlo, svhi);
        float sv = svlo + svhi + bdt;
        float delta, f;
        delta_f(sv, delta, f);
        S += delta;
        u64 q[8];
        pow_tree(f, q);
        u64 dud = dup2(delta * uu);
#pragma unroll
        for (int j = 0; j < 8; j++) {
            u64 Bp = *(const u64*)&sx[s][6 + 2 * j];
            h2[j] = fma2(h2[j], q[j], mul2(dud, Bp));
        }
    }
    size_t base = ((((size_t)(b * KD + k)) * NCH + c) * DD + d) * NS;
    float E = __expf(-S);
    u64 qp[8];
    pow_tree(E, qp);
#pragma unroll
    for (int j = 0; j < 8; j++) *(u64*)&g_P[base + 2 * j] = qp[j];
#pragma unroll
    for (int j = 0; j < 8; j++) *(u64*)&g_hend[base + 2 * j] = h2[j];
}

// ================= scan phase 1 (GENERIC fallback, early-exits) =================
__global__ void __launch_bounds__(192) scan_p1_gen(const float* __restrict__ dtw,
                                                   const float* __restrict__ dtb,
                                                   const float* __restrict__ Alogs) {
    int blk = blockIdx.x;
    int c = blk % NCH;
    int k = (blk / NCH) % KD;
    int b = blk / (NCH * KD);
    int d = threadIdx.x;

    bool powok = check_powok(Alogs, k, d);
    if (__syncthreads_and(powok)) return;

    float wdt[RR];
#pragma unroll
    for (int r = 0; r < RR; r++) wdt[r] = dtw[(k * DD + d) * RR + r];
    float bdt = dtb[k * DD + d];
    float A[NS];
#pragma unroll
    for (int n = 0; n < NS; n++) A[n] = -__expf(Alogs[(k * DD + d) * NS + n]);

    int p0, pstep;
    scan_affine(k, c, p0, pstep);

    __shared__ __align__(16) float sx[CHL][40];
    for (int i = d; i < CHL * 38; i += DD) {
        int s = i / 38, cc = i - s * 38;
        sx[s][cc] = g_xdbl[((size_t)(b * LS + p0 + s * pstep)) * XD + k * 38 + cc];
    }
    __syncthreads();
    if (powok) return;

    const float* up = g_u + ((size_t)(b * LS + p0)) * DD + d;
    int ustep = pstep * DD;
    float S = 0.f;
    float h[NS];
#pragma unroll
    for (int n = 0; n < NS; n++) h[n] = 0.f;
    for (int s = 0; s < CHL; s++) {
        float uu = *up; up += ustep;
        float sv = bdt;
#pragma unroll
        for (int r = 0; r < RR; r++) sv += sx[s][r] * wdt[r];
        float e = __expf(-fabsf(sv));
        float delta = fmaxf(sv, 0.f) + log1pf(e);
        S += delta;
        float du = delta * uu;
#pragma unroll
        for (int n = 0; n < NS; n++) {
            float dA = __expf(delta * A[n]);
            h[n] = h[n] * dA + du * sx[s][6 + n];
        }
    }
    size_t base = ((((size_t)(b * KD + k)) * NCH + c) * DD + d) * NS;
#pragma unroll
    for (int n = 0; n < NS; n++) { g_P[base + n] = __expf(A[n] * S); g_hend[base + n] = h[n]; }
}

// ---------------- scan phase 2: stitch chunk boundaries ----------------
__global__ void scan_p2() {
    int gid = blockIdx.x * blockDim.x + threadIdx.x;   // B*K*D*N = 24576
    int dn = gid % (DD * NS);
    int k = (gid / (DD * NS)) % KD;
    int b = gid / (DD * NS * KD);
    float h = 0.f;
    size_t stride = (size_t)DD * NS;
    size_t base = ((size_t)(b * KD + k)) * NCH * stride + dn;
    for (int c = 0; c < NCH; c++) {
        size_t idx = base + (size_t)c * stride;
        float Pv = g_P[idx];
        float he = g_hend[idx];
        g_P[idx] = h;
        h = Pv * h + he;
    }
}

// ================= scan phase 3 (FAST) =================
__global__ void __launch_bounds__(192, 5) scan_p3_fast(const float* __restrict__ dtw,
                                                       const float* __restrict__ dtb,
                                                       const float* __restrict__ Alogs,
                                                       const float* __restrict__ Ds) {
    int blk = blockIdx.x;
    int c = blk % NCH;
    int k = (blk / NCH) % KD;
    int b = blk / (NCH * KD);
    int d = threadIdx.x;

    bool powok = check_powok(Alogs, k, d);

    u64 wd2[3];
#pragma unroll
    for (int r = 0; r < 3; r++)
        wd2[r] = pk2(dtw[(k * DD + d) * RR + 2 * r], dtw[(k * DD + d) * RR + 2 * r + 1]);
    float bdt = dtb[k * DD + d];
    float Dsv = Ds[k * DD + d];

    int p0, pstep;
    scan_affine(k, c, p0, pstep);

    __shared__ __align__(16) float sx[CHL][40];
    for (int i = d; i < CHL * 38; i += DD) {
        int s = i / 38, cc = i - s * 38;
        sx[s][cc] = g_xdbl[((size_t)(b * LS + p0 + s * pstep)) * XD + k * 38 + cc];
    }
    __syncthreads();
    if (!powok) return;

    size_t base = ((((size_t)(b * KD + k)) * NCH + c) * DD + d) * NS;
    const float* up = g_u + ((size_t)(b * LS + p0)) * DD + d;
    int ustep = pstep * DD;
    float* oyp = g_oy + (((size_t)(b * KD + k)) * LS + c * CHL) * DD + d;

    u64 h2[8];
#pragma unroll
    for (int j = 0; j < 8; j++) h2[j] = *(const u64*)&g_P[base + 2 * j];
    for (int s = 0; s < CHL; s++) {
        float uu = *up; up += ustep;
        u64 sv2 = fma2(*(const u64*)&sx[s][0], wd2[0],
                  fma2(*(const u64*)&sx[s][2], wd2[1],
                  mul2(*(const u64*)&sx[s][4], wd2[2])));
        float svlo, svhi; unpk2(sv2, svlo, svhi);
        float sv = svlo + svhi + bdt;
        float delta, f;
        delta_f(sv, delta, f);
        u64 q[8];
        pow_tree(f, q);
        u64 dud = dup2(delta * uu);
        u64 y2 = 0ull;
#pragma unroll
        for (int j = 0; j < 8; j++) {
            u64 Bp = *(const u64*)&sx[s][6 + 2 * j];
            u64 Cp = *(const u64*)&sx[s][22 + 2 * j];
            h2[j] = fma2(h2[j], q[j], mul2(dud, Bp));
            y2 = fma2(h2[j], Cp, y2);
        }
        float ylo, yhi;
        unpk2(y2, ylo, yhi);
        *oyp = ylo + yhi + uu * Dsv;
        oyp += DD;
    }
}

// ================= scan phase 3 (GENERIC fallback, early-exits) =================
__global__ void __launch_bounds__(192) scan_p3_gen(const float* __restrict__ dtw,
                                                   const float* __restrict__ dtb,
                                                   const float* __restrict__ Alogs,
                                                   const float* __restrict__ Ds) {
    int blk = blockIdx.x;
    int c = blk % NCH;
    int k = (blk / NCH) % KD;
    int b = blk / (NCH * KD);
    int d = threadIdx.x;

    bool powok = check_powok(Alogs, k, d);
    if (__syncthreads_and(powok)) return;

    float wdt[RR];
#pragma unroll
    for (int r = 0; r < RR; r++) wdt[r] = dtw[(k * DD + d) * RR + r];
    float bdt = dtb[k * DD + d];
    float Dsv = Ds[k * DD + d];
    float A[NS];
#pragma unroll
    for (int n = 0; n < NS; n++) A[n] = -__expf(Alogs[(k * DD + d) * NS + n]);

    int p0, pstep;
    scan_affine(k, c, p0, pstep);

    __shared__ __align__(16) float sx[CHL][40];
    for (int i = d; i < CHL * 38; i += DD) {
        int s = i / 38, cc = i - s * 38;
        sx[s][cc] = g_xdbl[((size_t)(b * LS + p0 + s * pstep)) * XD + k * 38 + cc];
    }
    __syncthreads();
    if (powok) return;

    size_t base = ((((size_t)(b * KD + k)) * NCH + c) * DD + d) * NS;
    const float* up = g_u + ((size_t)(b * LS + p0)) * DD + d;
    int ustep = pstep * DD;
    float* oyp = g_oy + (((size_t)(b * KD + k)) * LS + c * CHL) * DD + d;

    float h[NS];
#pragma unroll
    for (int n = 0; n < NS; n++) h[n] = g_P[base + n];
    for (int s = 0; s < CHL; s++) {
        float uu = *up; up += ustep;
        float sv = bdt;
#pragma unroll
        for (int r = 0; r < RR; r++) sv += sx[s][r] * wdt[r];
        float e = __expf(-fabsf(sv));
        float delta = fmaxf(sv, 0.f) + log1pf(e);
        float du = delta * uu;
        float y = 0.f;
#pragma unroll
        for (int n = 0; n < NS; n++) {
            float dA = __expf(delta * A[n]);
            h[n] = h[n] * dA + du * sx[s][6 + n];
            y += h[n] * sx[s][22 + n];
        }
        *oyp = y + uu * Dsv;
        oyp += DD;
    }
}

// ---------------- combine 4 directions + LN(out_norm) + silu(z) gate -------------
__global__ void combine_ln_silu(const float* __restrict__ gno, const float* __restrict__ bno) {
    int warp = (blockIdx.x * blockDim.x + threadIdx.x) >> 5;
    int lane = threadIdx.x & 31;
    if (warp >= MPIX) return;
    int b = warp / LS, p = warp - b * LS;
    int hh = p / WW, ww = p - hh * WW;
    int tcol = ww * HH + hh;

    size_t base0 = (((size_t)(b * KD + 0)) * LS + p) * DD;
    size_t base1 = (((size_t)(b * KD + 1)) * LS + tcol) * DD;
    size_t base2 = (((size_t)(b * KD + 2)) * LS + (LS - 1 - p)) * DD;
    size_t base3 = (((size_t)(b * KD + 3)) * LS + (LS - 1 - tcol)) * DD;

    float v[6], s = 0.f, ss = 0.f;
#pragma unroll
    for (int j = 0; j < 6; j++) {
        int dd = lane + j * 32;
        float t = g_oy[base0 + dd] + g_oy[base1 + dd] + g_oy[base2 + dd] + g_oy[base3 + dd];
        v[j] = t; s += t; ss += t * t;
    }
#pragma unroll
    for (int o = 16; o > 0; o >>= 1) { s += __shfl_xor_sync(~0u, s, o); ss += __shfl_xor_sync(~0u, ss, o); }
    float m = s * (1.f / DD);
    float var = ss * (1.f / DD) - m * m;
    float inv = rsqrtf(var + 1e-5f);
#pragma unroll
    for (int j = 0; j < 6; j++) {
        int dd = lane + j * 32;
        float z = g_xz[((size_t)warp) * (2 * DD) + DD + dd];
        float yn = (v[j] - m) * inv * gno[dd] + bno[dd];
        g_ypost[(size_t)warp * DD + dd] = yn * siluf(z);
    }
}

// ---------------- residual 1 + LN_ffn ----------------
__global__ void resid1_lnffn(const float* __restrict__ x, const float* __restrict__ scale1,
                             const float* __restrict__ gf, const float* __restrict__ bf) {
    int warp = (blockIdx.x * blockDim.x + threadIdx.x) >> 5;
    int lane = threadIdx.x & 31;
    if (warp >= MPIX) return;
    int b = warp / LS, p = warp - b * LS;
    float v[3], s = 0.f, ss = 0.f;
#pragma unroll
    for (int j = 0; j < 3; j++) {
        int c = lane + j * 32;
        float t = g_t96[(size_t)warp * CC + c] + x[((size_t)(b * CC + c)) * LS + p] * scale1[c];
        v[j] = t; s += t; ss += t * t;
        g_x2[(size_t)warp * CC + c] = t;
    }
#pragma unroll
    for (int o = 16; o > 0; o >>= 1) { s += __shfl_xor_sync(~0u, s, o); ss += __shfl_xor_sync(~0u, ss, o); }
    float m = s * (1.f / CC);
    float var = ss * (1.f / CC) - m * m;
    float inv = rsqrtf(var + 1e-5f);
#pragma unroll
    for (int j = 0; j < 3; j++) {
        int c = lane + j * 32;
        g_h1n[(size_t)warp * CC + c] = (v[j] - m) * inv * gf[c] + bf[c];
    }
}

// ---------------- final: residual 2 + tiled transpose to (B,C,H,W) ----------------
__global__ void __launch_bounds__(256) final_kernel(const float* __restrict__ scale2,
                                                    float* __restrict__ out) {
    __shared__ float tile[CC][33];
    int b = blockIdx.y;
    int p0 = blockIdx.x * 32;
    int t = threadIdx.x;
    for (int idx = t; idx < 32 * CC; idx += 256) {
        int i = idx / CC;
        int c = idx - i * CC;
        size_t src = ((size_t)(b * LS + p0 + i)) * CC + c;
        tile[c][i] = g_t96[src] + g_x2[src] * scale2[c];
    }
    __syncthreads();
    for (int idx = t; idx < 32 * CC; idx += 256) {
        int c = idx >> 5;
        int i = idx & 31;
        out[((size_t)(b * CC + c)) * LS + p0 + i] = tile[c][i];
    }
}

// ---------------- launch ----------------
extern "C" void kernel_launch(void* const* d_in, const int* in_sizes, int n_in,
                              void* d_out, int out_size) {
    const float* x          = (const float*)d_in[0];
    const float* ln_in_g    = (const float*)d_in[1];
    const float* ln_in_b    = (const float*)d_in[2];
    const float* in_proj_w  = (const float*)d_in[3];
    const float* in_proj_b  = (const float*)d_in[4];
    const float* conv_w     = (const float*)d_in[5];
    const float* conv_b     = (const float*)d_in[6];
    const float* x_proj_w   = (const float*)d_in[7];
    const float* dt_w       = (const float*)d_in[8];
    const float* dt_b       = (const float*)d_in[9];
    const float* A_logs     = (const float*)d_in[10];
    const float* Ds         = (const float*)d_in[11];
    const float* out_norm_g = (const float*)d_in[12];
    const float* out_norm_b = (const float*)d_in[13];
    const float* out_proj_w = (const float*)d_in[14];
    const float* out_proj_b = (const float*)d_in[15];
    const float* ln_ffn_g   = (const float*)d_in[16];
    const float* ln_ffn_b   = (const float*)d_in[17];
    const float* fc1_w      = (const float*)d_in[18];
    const float* fc1_b      = (const float*)d_in[19];
    const float* fc2_w      = (const float*)d_in[20];
    const float* fc2_b      = (const float*)d_in[21];
    const float* scale1     = (const float*)d_in[22];
    const float* scale2     = (const float*)d_in[23];

    float *p_xn, *p_xz, *p_u, *p_xdbl, *p_ypost, *p_t96, *p_h1n, *p_t192;
    cudaGetSymbolAddress((void**)&p_xn,    g_xn);
    cudaGetSymbolAddress((void**)&p_xz,    g_xz);
    cudaGetSymbolAddress((void**)&p_u,     g_u);
    cudaGetSymbolAddress((void**)&p_xdbl,  g_xdbl);
    cudaGetSymbolAddress((void**)&p_ypost, g_ypost);
    cudaGetSymbolAddress((void**)&p_t96,   g_t96);
    cudaGetSymbolAddress((void**)&p_h1n,   g_h1n);
    cudaGetSymbolAddress((void**)&p_t192,  g_t192);

    const int MB = MPIX / 128;   // 144

    // 1. LN over channels -> g_xn (B,L,C)
    ln_in_kernel<<<MPIX / 8, 256>>>(x, ln_in_g, ln_in_b);
    // 2. in_proj: (M,96)x(384,96)^T  [tf32 tensor cores]
    gemm_tc<0><<<dim3(384 / 32, MB), 256>>>(p_xn, in_proj_w, in_proj_b, p_xz, MPIX, 2 * DD, CC);
    // 3. depthwise conv 3x3 + SiLU
    conv_silu_kernel<<<MPIX, DD>>>(conv_w, conv_b);
    // 4. x_proj: (M,192)x(152,192)^T
    gemm_tc<0><<<dim3((XD + 31) / 32, MB), 256>>>(p_u, x_proj_w, nullptr, p_xdbl, MPIX, XD, DD);
    // 5-7. chunked selective scan (fast + generic-fallback pairs)
    scan_p1_fast<<<BSZ * KD * NCH, DD>>>(dt_w, dt_b, A_logs);
    scan_p1_gen <<<BSZ * KD * NCH, DD>>>(dt_w, dt_b, A_logs);
    scan_p2<<<(BSZ * KD * DD * NS) / 256, 256>>>();
    scan_p3_fast<<<BSZ * KD * NCH, DD>>>(dt_w, dt_b, A_logs, Ds);
    scan_p3_gen <<<BSZ * KD * NCH, DD>>>(dt_w, dt_b, A_logs, Ds);
    // 8. combine + LN + gate
    combine_ln_silu<<<MPIX / 8, 256>>>(out_norm_g, out_norm_b);
    // 9. out_proj: (M,192)x(96,192)^T
    gemm_tc<0><<<dim3(CC / 32, MB), 256>>>(p_ypost, out_proj_w, out_proj_b, p_t96, MPIX, CC, DD);
    // 10. residual1 + LN_ffn
    resid1_lnffn<<<MPIX / 8, 256>>>(x, scale1, ln_ffn_g, ln_ffn_b);
    // 11. fc1 + leaky relu
    gemm_tc<1><<<dim3(DD / 32, MB), 256>>>(p_h1n, fc1_w, fc1_b, p_t192, MPIX, DD, CC);
    // 12. fc2
    gemm_tc<0><<<dim3(CC / 32, MB), 256>>>(p_t192, fc2_w, fc2_b, p_t96, MPIX, CC, DD);
    // 13. residual2 + transpose to (B,C,H,W)
    final_kernel<<<dim3(LS / 32, BSZ), 256>>>(scale2, (float*)d_out);
}